// round 10
// baseline (speedup 1.0000x reference)
#include <cuda_runtime.h>
#include <cuda_bf16.h>
#include <stdint.h>

#define B_  8
#define H_  8
#define M_  512
#define N_  512
#define DD  64
#define HID 16

#define BM 128
#define BN 64
#define THREADS 256
#define NTILES (N_ / BN)
#define LOG2E 1.44269504088896340736f

// interleaved hi/lo tiles: row stride 72 u32 words (32 word-pairs + 8 pad)
// word-pair p of a row: [2p]=hi(bf16x2), [2p+1]=lo(bf16x2)
#define W_Q 0          // [128][72]
#define W_K 9216       // [64][72]
#define W_V 13824      // V^T [64 d][72], col pair XOR-swizzled
#define SMEM_WORDS 18432
#define SMEM_BYTES (SMEM_WORDS * 4)

typedef unsigned long long ull;

__device__ __forceinline__ ull fma2(ull a, ull b, ull c) {
    ull d; asm("fma.rn.f32x2 %0,%1,%2,%3;" : "=l"(d) : "l"(a), "l"(b), "l"(c)); return d;
}
__device__ __forceinline__ ull pk(float x, float y) {
    ull r; asm("mov.b64 %0,{%1,%2};" : "=l"(r) : "f"(x), "f"(y)); return r;
}
__device__ __forceinline__ void upk(ull a, float& x, float& y) {
    asm("mov.b64 {%0,%1},%2;" : "=f"(x), "=f"(y) : "l"(a));
}
__device__ __forceinline__ ull relu2(ull a) {
    float x, y; upk(a, x, y);
    return pk(fmaxf(x, 0.0f), fmaxf(y, 0.0f));
}
// pack two f32 -> bf16x2 (x in LOW half, matching fragment col-even-in-low)
__device__ __forceinline__ uint32_t cvt2(float x, float y) {
    uint32_t r; asm("cvt.rn.bf16x2.f32 %0, %1, %2;" : "=r"(r) : "f"(y), "f"(x)); return r;
}
__device__ __forceinline__ float lo16f(uint32_t w) { return __uint_as_float(w << 16); }
__device__ __forceinline__ float hi16f(uint32_t w) { return __uint_as_float(w & 0xffff0000u); }
__device__ __forceinline__ uint32_t lo32(ull a) { return (uint32_t)a; }
__device__ __forceinline__ uint32_t hi32(ull a) { return (uint32_t)(a >> 32); }

// D += A * B   (m16n8k16 row.col, bf16 in, f32 accum)
__device__ __forceinline__ void mma16816(float* d, const uint32_t* a, uint32_t b0, uint32_t b1) {
    asm volatile(
        "mma.sync.aligned.m16n8k16.row.col.f32.bf16.bf16.f32 "
        "{%0,%1,%2,%3}, {%4,%5,%6,%7}, {%8,%9}, {%0,%1,%2,%3};"
        : "+f"(d[0]), "+f"(d[1]), "+f"(d[2]), "+f"(d[3])
        : "r"(a[0]), "r"(a[1]), "r"(a[2]), "r"(a[3]), "r"(b0), "r"(b1));
}

__global__ __launch_bounds__(THREADS, 2)
void msdpa_mma_kernel(const float* __restrict__ q,
                      const float* __restrict__ k,
                      const float* __restrict__ v,
                      const float* __restrict__ dmat,
                      const float* __restrict__ mixW1,
                      const float* __restrict__ mixb1,
                      const float* __restrict__ mixW2,
                      const float* __restrict__ mixb2,
                      float* __restrict__ out)
{
    extern __shared__ uint32_t sm[];
    uint32_t* Qi = sm + W_Q;
    uint32_t* Ki = sm + W_K;
    uint32_t* Vi = sm + W_V;

    __shared__ __align__(16) float sWp[HID * 8];
    __shared__ float sB2;

    const int tid  = threadIdx.x;
    const int wid  = tid >> 5;
    const int lane = tid & 31;
    const int g    = lane >> 2;
    const int tig  = lane & 3;

    const int b  = blockIdx.z;
    const int h  = blockIdx.y;
    const int m0 = blockIdx.x * BM;

    const float* qb = q + ((size_t)(b * H_ + h) * M_ + m0) * DD;
    const float* kb = k + (size_t)(b * H_ + h) * N_ * DD;
    const float* vb = v + (size_t)(b * H_ + h) * N_ * DD;

    if (tid < HID) {
        const float scale = 0.125f;
        float a = mixW1[(h * 2 + 0) * HID + tid] * scale;
        float c = mixW1[(h * 2 + 1) * HID + tid];
        float e = mixb1[h * HID + tid];
        float w = mixW2[h * HID + tid] * LOG2E;
        float* wp = sWp + tid * 8;
        wp[0] = a; wp[1] = a; wp[2] = c; wp[3] = c;
        wp[4] = e; wp[5] = e; wp[6] = w; wp[7] = w;
    }
    if (tid == 0) sB2 = mixb2[h] * LOG2E;

    // ---- stage Q once: interleaved hi/lo, uint4 stores ----
    {
        int row = tid >> 1;
        int p0  = (tid & 1) * 16;              // word-pair base
        const float* qr = qb + row * DD + (tid & 1) * 32;
        #pragma unroll
        for (int i = 0; i < 8; i++) {
            float4 f = ((const float4*)qr)[i];
            uint32_t h0 = cvt2(f.x, f.y);
            uint32_t l0 = cvt2(f.x - lo16f(h0), f.y - hi16f(h0));
            uint32_t h1 = cvt2(f.z, f.w);
            uint32_t l1 = cvt2(f.z - lo16f(h1), f.w - hi16f(h1));
            *(uint4*)(Qi + row * 72 + 2 * (p0 + 2 * i)) = make_uint4(h0, l0, h1, l1);
        }
    }

    float Od[8][4];
    #pragma unroll
    for (int d = 0; d < 8; d++)
        #pragma unroll
        for (int e = 0; e < 4; e++) Od[d][e] = 0.0f;
    float rs0 = 0.0f, rs1 = 0.0f;

    __syncthreads();
    const ull b2p = pk(sB2, sB2);

    const int r0w = (wid * 16 + g) * 72;
    const int r1w = r0w + 8 * 72;
    const float* dm0 = dmat + ((size_t)b * M_ + m0 + wid * 16 + g) * N_;

    for (int t = 0; t < NTILES; t++) {
        // ---- stage K tile ----
        {
            int key = tid >> 2;
            int p0  = (tid & 3) * 8;
            const float* kr = kb + (size_t)(t * BN + key) * DD + (tid & 3) * 16;
            #pragma unroll
            for (int i = 0; i < 4; i++) {
                float4 f = ((const float4*)kr)[i];
                uint32_t h0 = cvt2(f.x, f.y);
                uint32_t l0 = cvt2(f.x - lo16f(h0), f.y - hi16f(h0));
                uint32_t h1 = cvt2(f.z, f.w);
                uint32_t l1 = cvt2(f.z - lo16f(h1), f.w - hi16f(h1));
                *(uint4*)(Ki + key * 72 + 2 * (p0 + 2 * i)) = make_uint4(h0, l0, h1, l1);
            }
        }
        // ---- stage V^T tile (col pair XOR-swizzled by (d>>3)<<2) ----
        {
            int kp = tid >> 3;
            int a  = tid & 7;
            int d0 = a * 8;
            const float* v0 = vb + (size_t)(t * BN + 2 * kp) * DD + d0;
            const float* v1 = v0 + DD;
            float4 f0a = ((const float4*)v0)[0], f0b = ((const float4*)v0)[1];
            float4 f1a = ((const float4*)v1)[0], f1b = ((const float4*)v1)[1];
            float e0[8] = {f0a.x, f0a.y, f0a.z, f0a.w, f0b.x, f0b.y, f0b.z, f0b.w};
            float e1[8] = {f1a.x, f1a.y, f1a.z, f1a.w, f1b.x, f1b.y, f1b.z, f1b.w};
            int colp = kp ^ (a << 2);
            #pragma unroll
            for (int i = 0; i < 8; i++) {
                uint32_t hw = cvt2(e0[i], e1[i]);     // lo: key 2kp, hi: key 2kp+1
                uint32_t lw = cvt2(e0[i] - lo16f(hw), e1[i] - hi16f(hw));
                *(ull*)(Vi + (d0 + i) * 72 + 2 * colp) = ((ull)lw << 32) | hw;
            }
        }
        __syncthreads();

        // ---- S = Q K^T via 3-product split mma; frags via LDS.64 ----
        float S[8][4];
        #pragma unroll
        for (int n = 0; n < 8; n++)
            #pragma unroll
            for (int e = 0; e < 4; e++) S[n][e] = 0.0f;

        #pragma unroll
        for (int kc = 0; kc < 4; kc++) {
            int wq = 2 * (kc * 8 + tig);
            ull q0 = *(const ull*)(Qi + r0w + wq);
            ull q1 = *(const ull*)(Qi + r1w + wq);
            ull q2 = *(const ull*)(Qi + r0w + wq + 8);
            ull q3 = *(const ull*)(Qi + r1w + wq + 8);
            uint32_t qh[4] = {lo32(q0), lo32(q1), lo32(q2), lo32(q3)};
            uint32_t ql[4] = {hi32(q0), hi32(q1), hi32(q2), hi32(q3)};
            #pragma unroll
            for (int n = 0; n < 8; n++) {
                const uint32_t* kw = Ki + (n * 8 + g) * 72 + wq;
                ull kb0 = *(const ull*)kw;
                ull kb1 = *(const ull*)(kw + 8);
                uint32_t bh0 = lo32(kb0), bl0 = hi32(kb0);
                uint32_t bh1 = lo32(kb1), bl1 = hi32(kb1);
                mma16816(S[n], qh, bh0, bh1);
                mma16816(S[n], qh, bl0, bl1);
                mma16816(S[n], ql, bh0, bh1);
            }
        }

        // ---- MLP + exp2 (unnormalized), n chunked by 2 (f inner -> weight LDS /2) ----
        uint32_t PhiA[8], PhiB[8], PloA[8], PloB[8];
        #pragma unroll
        for (int n0 = 0; n0 < 8; n0 += 2) {
            ull ms01[2], ms23[2], dm01[2], dm23[2], a01[2], a23[2];
            #pragma unroll
            for (int e = 0; e < 2; e++) {
                int n = n0 + e;
                int col = t * BN + n * 8 + tig * 2;
                float2 dA = *(const float2*)(dm0 + col);
                float2 dB = *(const float2*)(dm0 + 8 * N_ + col);
                ms01[e] = pk(S[n][0], S[n][1]);
                ms23[e] = pk(S[n][2], S[n][3]);
                dm01[e] = pk(dA.x, dA.y);
                dm23[e] = pk(dB.x, dB.y);
                a01[e] = b2p; a23[e] = b2p;
            }
            #pragma unroll
            for (int f = 0; f < HID; f++) {
                const ull w1s = *(const ull*)(sWp + f * 8 + 0);
                const ull w1d = *(const ull*)(sWp + f * 8 + 2);
                const ull bb  = *(const ull*)(sWp + f * 8 + 4);
                const ull w2  = *(const ull*)(sWp + f * 8 + 6);
                #pragma unroll
                for (int e = 0; e < 2; e++) {
                    a01[e] = fma2(w2, relu2(fma2(w1s, ms01[e], fma2(w1d, dm01[e], bb))), a01[e]);
                    a23[e] = fma2(w2, relu2(fma2(w1s, ms23[e], fma2(w1d, dm23[e], bb))), a23[e]);
                }
            }
            #pragma unroll
            for (int e = 0; e < 2; e++) {
                int n = n0 + e;
                float p0, p1, p2, p3;
                upk(a01[e], p0, p1); upk(a23[e], p2, p3);
                p0 = exp2f(p0); p1 = exp2f(p1); p2 = exp2f(p2); p3 = exp2f(p3);
                rs0 += p0 + p1;
                rs1 += p2 + p3;
                uint32_t hA = cvt2(p0, p1);
                PhiA[n] = hA;
                PloA[n] = cvt2(p0 - lo16f(hA), p1 - hi16f(hA));
                uint32_t hB = cvt2(p2, p3);
                PhiB[n] = hB;
                PloB[n] = cvt2(p2 - lo16f(hB), p3 - hi16f(hB));
            }
        }

        // ---- O += P V via 3-product split mma; V frags via LDS.64 ----
        #pragma unroll
        for (int kc = 0; kc < 4; kc++) {
            uint32_t ah[4] = {PhiA[2 * kc], PhiB[2 * kc], PhiA[2 * kc + 1], PhiB[2 * kc + 1]};
            uint32_t al[4] = {PloA[2 * kc], PloB[2 * kc], PloA[2 * kc + 1], PloB[2 * kc + 1]};
            #pragma unroll
            for (int dt = 0; dt < 8; dt++) {
                int row = (dt * 8 + g) * 72;
                ull v0 = *(const ull*)(Vi + row + 2 * ((kc * 8 + tig) ^ (dt << 2)));
                ull v1 = *(const ull*)(Vi + row + 2 * ((kc * 8 + tig + 4) ^ (dt << 2)));
                uint32_t bh0 = lo32(v0), bl0 = hi32(v0);
                uint32_t bh1 = lo32(v1), bl1 = hi32(v1);
                mma16816(Od[dt], ah, bh0, bh1);
                mma16816(Od[dt], ah, bl0, bl1);
                mma16816(Od[dt], al, bh0, bh1);
            }
        }
        __syncthreads();
    }

    // ---- epilogue: quad-reduce row sums, normalize, store ----
    const unsigned FULL = 0xffffffffu;
    rs0 += __shfl_xor_sync(FULL, rs0, 1);
    rs0 += __shfl_xor_sync(FULL, rs0, 2);
    rs1 += __shfl_xor_sync(FULL, rs1, 1);
    rs1 += __shfl_xor_sync(FULL, rs1, 2);
    float i0 = 1.0f / rs0;
    float i1 = 1.0f / rs1;

    float* o0 = out + ((size_t)(b * H_ + h) * M_ + m0 + wid * 16 + g) * DD;
    float* o1 = o0 + 8 * DD;
    #pragma unroll
    for (int dt = 0; dt < 8; dt++) {
        *(float2*)(o0 + dt * 8 + tig * 2) = make_float2(Od[dt][0] * i0, Od[dt][1] * i0);
        *(float2*)(o1 + dt * 8 + tig * 2) = make_float2(Od[dt][2] * i1, Od[dt][3] * i1);
    }
}

extern "C" void kernel_launch(void* const* d_in, const int* in_sizes, int n_in,
                              void* d_out, int out_size)
{
    const float* q     = (const float*)d_in[0];
    const float* k     = (const float*)d_in[1];
    const float* v     = (const float*)d_in[2];
    const float* dmat  = (const float*)d_in[3];
    const float* mixW1 = (const float*)d_in[4];
    const float* mixb1 = (const float*)d_in[5];
    const float* mixW2 = (const float*)d_in[6];
    const float* mixb2 = (const float*)d_in[7];
    float* out = (float*)d_out;

    cudaFuncSetAttribute(msdpa_mma_kernel,
                         cudaFuncAttributeMaxDynamicSharedMemorySize, SMEM_BYTES);

    dim3 grid(M_ / BM, H_, B_);   // (4, 8, 8)
    msdpa_mma_kernel<<<grid, THREADS, SMEM_BYTES>>>(q, k, v, dmat,
                                                    mixW1, mixb1, mixW2, mixb2, out);
}

// round 11
// speedup vs baseline: 1.0570x; 1.0570x over previous
#include <cuda_runtime.h>
#include <cuda_bf16.h>
#include <stdint.h>

#define B_  8
#define H_  8
#define M_  512
#define N_  512
#define DD  64
#define HID 16

#define BM 128
#define BN 64
#define THREADS 256
#define NTILES (N_ / BN)
#define LOG2E 1.44269504088896340736f

// smem word (u32) offsets; rows are 36 words (32 data + 4 pad) for conflict-free frags
#define W_QHI 0          // [128][36]
#define W_QLO 4608
#define W_KHI 9216       // [64][36]
#define W_KLO 11520
#define W_VTHI 13824     // V^T [64 d][36] (cols = key-pair words, XOR-swizzled)
#define W_VTLO 16128
#define SMEM_WORDS 18432
#define SMEM_BYTES (SMEM_WORDS * 4)

typedef unsigned long long ull;

__device__ __forceinline__ ull fma2(ull a, ull b, ull c) {
    ull d; asm("fma.rn.f32x2 %0,%1,%2,%3;" : "=l"(d) : "l"(a), "l"(b), "l"(c)); return d;
}
__device__ __forceinline__ ull pk(float x, float y) {
    ull r; asm("mov.b64 %0,{%1,%2};" : "=l"(r) : "f"(x), "f"(y)); return r;
}
__device__ __forceinline__ void upk(ull a, float& x, float& y) {
    asm("mov.b64 {%0,%1},%2;" : "=f"(x), "=f"(y) : "l"(a));
}
__device__ __forceinline__ ull relu2(ull a) {
    float x, y; upk(a, x, y);
    return pk(fmaxf(x, 0.0f), fmaxf(y, 0.0f));
}
// pack two f32 -> bf16x2 (x in LOW half, matching fragment col-even-in-low)
__device__ __forceinline__ uint32_t cvt2(float x, float y) {
    uint32_t r; asm("cvt.rn.bf16x2.f32 %0, %1, %2;" : "=r"(r) : "f"(y), "f"(x)); return r;
}
__device__ __forceinline__ float lo16f(uint32_t w) { return __uint_as_float(w << 16); }
__device__ __forceinline__ float hi16f(uint32_t w) { return __uint_as_float(w & 0xffff0000u); }

// D += A * B   (m16n8k16 row.col, bf16 in, f32 accum)
__device__ __forceinline__ void mma16816(float* d, const uint32_t* a, uint32_t b0, uint32_t b1) {
    asm volatile(
        "mma.sync.aligned.m16n8k16.row.col.f32.bf16.bf16.f32 "
        "{%0,%1,%2,%3}, {%4,%5,%6,%7}, {%8,%9}, {%0,%1,%2,%3};"
        : "+f"(d[0]), "+f"(d[1]), "+f"(d[2]), "+f"(d[3])
        : "r"(a[0]), "r"(a[1]), "r"(a[2]), "r"(a[3]), "r"(b0), "r"(b1));
}

__global__ __launch_bounds__(THREADS, 2)
void msdpa_mma_kernel(const float* __restrict__ q,
                      const float* __restrict__ k,
                      const float* __restrict__ v,
                      const float* __restrict__ dmat,
                      const float* __restrict__ mixW1,
                      const float* __restrict__ mixb1,
                      const float* __restrict__ mixW2,
                      const float* __restrict__ mixb2,
                      float* __restrict__ out)
{
    extern __shared__ uint32_t sm[];
    uint32_t* Qhi = sm + W_QHI;
    uint32_t* Qlo = sm + W_QLO;
    uint32_t* Khi = sm + W_KHI;
    uint32_t* Klo = sm + W_KLO;
    uint32_t* Vthi = sm + W_VTHI;
    uint32_t* Vtlo = sm + W_VTLO;

    __shared__ __align__(16) float sWp[HID * 8];
    __shared__ float sB2;

    const int tid  = threadIdx.x;
    const int wid  = tid >> 5;
    const int lane = tid & 31;
    const int g    = lane >> 2;
    const int tig  = lane & 3;

    const int b  = blockIdx.z;
    const int h  = blockIdx.y;
    const int m0 = blockIdx.x * BM;

    const float* qb = q + ((size_t)(b * H_ + h) * M_ + m0) * DD;
    const float* kb = k + (size_t)(b * H_ + h) * N_ * DD;
    const float* vb = v + (size_t)(b * H_ + h) * N_ * DD;

    if (tid < HID) {
        const float scale = 0.125f;
        float a = mixW1[(h * 2 + 0) * HID + tid] * scale;
        float c = mixW1[(h * 2 + 1) * HID + tid];
        float e = mixb1[h * HID + tid];
        float w = mixW2[h * HID + tid] * LOG2E;
        float* wp = sWp + tid * 8;
        wp[0] = a; wp[1] = a; wp[2] = c; wp[3] = c;
        wp[4] = e; wp[5] = e; wp[6] = w; wp[7] = w;
    }
    if (tid == 0) sB2 = mixb2[h] * LOG2E;

    // ---- stage Q (hi/lo split) once: [128 rows][32 words], stride 36 ----
    {
        int row = tid >> 1;
        int c0  = (tid & 1) * 16;
        const float* qr = qb + row * DD + (tid & 1) * 32;
        #pragma unroll
        for (int i = 0; i < 8; i++) {
            float4 f = ((const float4*)qr)[i];
            uint32_t h0 = cvt2(f.x, f.y);
            uint32_t l0 = cvt2(f.x - lo16f(h0), f.y - hi16f(h0));
            uint32_t h1 = cvt2(f.z, f.w);
            uint32_t l1 = cvt2(f.z - lo16f(h1), f.w - hi16f(h1));
            int w = row * 36 + c0 + i * 2;
            Qhi[w] = h0; Qhi[w + 1] = h1;
            Qlo[w] = l0; Qlo[w + 1] = l1;
        }
    }

    float Od[8][4];
    #pragma unroll
    for (int d = 0; d < 8; d++)
        #pragma unroll
        for (int e = 0; e < 4; e++) Od[d][e] = 0.0f;
    float rs0 = 0.0f, rs1 = 0.0f;

    __syncthreads();
    const ull b2p = pk(sB2, sB2);

    const int r0w = (wid * 16 + g) * 36;
    const int r1w = r0w + 8 * 36;
    const float* dm0 = dmat + ((size_t)b * M_ + m0 + wid * 16 + g) * N_;

    for (int t = 0; t < NTILES; t++) {
        // ---- stage K tile [64][64] hi/lo ----
        {
            int key = tid >> 2;
            int c0  = (tid & 3) * 8;
            const float* kr = kb + (size_t)(t * BN + key) * DD + (tid & 3) * 16;
            #pragma unroll
            for (int i = 0; i < 4; i++) {
                float4 f = ((const float4*)kr)[i];
                uint32_t h0 = cvt2(f.x, f.y);
                uint32_t l0 = cvt2(f.x - lo16f(h0), f.y - hi16f(h0));
                uint32_t h1 = cvt2(f.z, f.w);
                uint32_t l1 = cvt2(f.z - lo16f(h1), f.w - hi16f(h1));
                int w = key * 36 + c0 + i * 2;
                Khi[w] = h0; Khi[w + 1] = h1;
                Klo[w] = l0; Klo[w + 1] = l1;
            }
        }
        // ---- stage V^T tile: Vt[d][keypair-word], col XOR-swizzled by (d>>3)<<2 ----
        {
            int kp = tid >> 3;
            int a  = tid & 7;
            int d0 = a * 8;
            const float* v0 = vb + (size_t)(t * BN + 2 * kp) * DD + d0;
            const float* v1 = v0 + DD;
            float4 f0a = ((const float4*)v0)[0], f0b = ((const float4*)v0)[1];
            float4 f1a = ((const float4*)v1)[0], f1b = ((const float4*)v1)[1];
            float e0[8] = {f0a.x, f0a.y, f0a.z, f0a.w, f0b.x, f0b.y, f0b.z, f0b.w};
            float e1[8] = {f1a.x, f1a.y, f1a.z, f1a.w, f1b.x, f1b.y, f1b.z, f1b.w};
            int colp = kp ^ (a << 2);
            #pragma unroll
            for (int i = 0; i < 8; i++) {
                uint32_t hw = cvt2(e0[i], e1[i]);   // lo: key 2kp, hi: key 2kp+1
                uint32_t lw = cvt2(e0[i] - lo16f(hw), e1[i] - hi16f(hw));
                Vthi[(d0 + i) * 36 + colp] = hw;
                Vtlo[(d0 + i) * 36 + colp] = lw;
            }
        }
        __syncthreads();

        // ---- S = Q K^T via 3-product split mma ----
        float S[8][4];
        #pragma unroll
        for (int n = 0; n < 8; n++)
            #pragma unroll
            for (int e = 0; e < 4; e++) S[n][e] = 0.0f;

        #pragma unroll
        for (int kc = 0; kc < 4; kc++) {
            int wq = kc * 8 + tig;
            uint32_t qh[4] = {Qhi[r0w + wq], Qhi[r1w + wq], Qhi[r0w + wq + 4], Qhi[r1w + wq + 4]};
            uint32_t ql[4] = {Qlo[r0w + wq], Qlo[r1w + wq], Qlo[r0w + wq + 4], Qlo[r1w + wq + 4]};
            #pragma unroll
            for (int n = 0; n < 8; n++) {
                int wb = (n * 8 + g) * 36 + kc * 8 + tig;
                uint32_t bh0 = Khi[wb], bh1 = Khi[wb + 4];
                uint32_t bl0 = Klo[wb], bl1 = Klo[wb + 4];
                mma16816(S[n], qh, bh0, bh1);
                mma16816(S[n], qh, bl0, bl1);
                mma16816(S[n], ql, bh0, bh1);
            }
        }

        // ---- MLP + exp2 (unnormalized), n chunked by 4, f inner (weight LDS /4) ----
        uint32_t PhiA[8], PhiB[8], PloA[8], PloB[8];
        #pragma unroll
        for (int n0 = 0; n0 < 8; n0 += 4) {
            ull ms01[4], ms23[4], dm01[4], dm23[4], a01[4], a23[4];
            #pragma unroll
            for (int e = 0; e < 4; e++) {
                int n = n0 + e;
                int col = t * BN + n * 8 + tig * 2;
                float2 dA = *(const float2*)(dm0 + col);
                float2 dB = *(const float2*)(dm0 + 8 * N_ + col);
                ms01[e] = pk(S[n][0], S[n][1]);
                ms23[e] = pk(S[n][2], S[n][3]);
                dm01[e] = pk(dA.x, dA.y);
                dm23[e] = pk(dB.x, dB.y);
                a01[e] = b2p; a23[e] = b2p;
            }
            #pragma unroll
            for (int f = 0; f < HID; f++) {
                const ull w1s = *(const ull*)(sWp + f * 8 + 0);
                const ull w1d = *(const ull*)(sWp + f * 8 + 2);
                const ull bb  = *(const ull*)(sWp + f * 8 + 4);
                const ull w2  = *(const ull*)(sWp + f * 8 + 6);
                #pragma unroll
                for (int e = 0; e < 4; e++) {
                    a01[e] = fma2(w2, relu2(fma2(w1s, ms01[e], fma2(w1d, dm01[e], bb))), a01[e]);
                    a23[e] = fma2(w2, relu2(fma2(w1s, ms23[e], fma2(w1d, dm23[e], bb))), a23[e]);
                }
            }
            #pragma unroll
            for (int e = 0; e < 4; e++) {
                int n = n0 + e;
                float p0, p1, p2, p3;
                upk(a01[e], p0, p1); upk(a23[e], p2, p3);
                p0 = exp2f(p0); p1 = exp2f(p1); p2 = exp2f(p2); p3 = exp2f(p3);
                rs0 += p0 + p1;
                rs1 += p2 + p3;
                uint32_t hA = cvt2(p0, p1);
                PhiA[n] = hA;
                PloA[n] = cvt2(p0 - lo16f(hA), p1 - hi16f(hA));
                uint32_t hB = cvt2(p2, p3);
                PhiB[n] = hB;
                PloB[n] = cvt2(p2 - lo16f(hB), p3 - hi16f(hB));
            }
        }

        // ---- O += P V via 3-product split mma (P frags straight from registers) ----
        #pragma unroll
        for (int kc = 0; kc < 4; kc++) {
            uint32_t ah[4] = {PhiA[2 * kc], PhiB[2 * kc], PhiA[2 * kc + 1], PhiB[2 * kc + 1]};
            uint32_t al[4] = {PloA[2 * kc], PloB[2 * kc], PloA[2 * kc + 1], PloB[2 * kc + 1]};
            #pragma unroll
            for (int dt = 0; dt < 8; dt++) {
                int row = dt * 8 + g;
                int w0 = row * 36 + ((kc * 8 + tig) ^ (dt << 2));
                int w1 = row * 36 + ((kc * 8 + tig + 4) ^ (dt << 2));
                uint32_t bh0 = Vthi[w0], bh1 = Vthi[w1];
                uint32_t bl0 = Vtlo[w0], bl1 = Vtlo[w1];
                mma16816(Od[dt], ah, bh0, bh1);
                mma16816(Od[dt], ah, bl0, bl1);
                mma16816(Od[dt], al, bh0, bh1);
            }
        }
        __syncthreads();
    }

    // ---- epilogue: quad-reduce row sums, normalize, store ----
    const unsigned FULL = 0xffffffffu;
    rs0 += __shfl_xor_sync(FULL, rs0, 1);
    rs0 += __shfl_xor_sync(FULL, rs0, 2);
    rs1 += __shfl_xor_sync(FULL, rs1, 1);
    rs1 += __shfl_xor_sync(FULL, rs1, 2);
    float i0 = 1.0f / rs0;
    float i1 = 1.0f / rs1;

    float* o0 = out + ((size_t)(b * H_ + h) * M_ + m0 + wid * 16 + g) * DD;
    float* o1 = o0 + 8 * DD;
    #pragma unroll
    for (int dt = 0; dt < 8; dt++) {
        *(float2*)(o0 + dt * 8 + tig * 2) = make_float2(Od[dt][0] * i0, Od[dt][1] * i0);
        *(float2*)(o1 + dt * 8 + tig * 2) = make_float2(Od[dt][2] * i1, Od[dt][3] * i1);
    }
}

extern "C" void kernel_launch(void* const* d_in, const int* in_sizes, int n_in,
                              void* d_out, int out_size)
{
    const float* q     = (const float*)d_in[0];
    const float* k     = (const float*)d_in[1];
    const float* v     = (const float*)d_in[2];
    const float* dmat  = (const float*)d_in[3];
    const float* mixW1 = (const float*)d_in[4];
    const float* mixb1 = (const float*)d_in[5];
    const float* mixW2 = (const float*)d_in[6];
    const float* mixb2 = (const float*)d_in[7];
    float* out = (float*)d_out;

    cudaFuncSetAttribute(msdpa_mma_kernel,
                         cudaFuncAttributeMaxDynamicSharedMemorySize, SMEM_BYTES);

    dim3 grid(M_ / BM, H_, B_);   // (4, 8, 8)
    msdpa_mma_kernel<<<grid, THREADS, SMEM_BYTES>>>(q, k, v, dmat,
                                                    mixW1, mixb1, mixW2, mixb2, out);
}